// round 9
// baseline (speedup 1.0000x reference)
#include <cuda_runtime.h>
#include <cuda_bf16.h>
#include <stdint.h>

// Dataset-fixed: N=100000, T=25, DEGS=4, G=512, E=8000000
#define TPB    256
#define VEC    4                     // edges per thread per inner iteration
#define ITERS  4                     // inner iterations per tile
#define TILE   (TPB * VEC * ITERS)   // 4096 edges per block
#define NMAX   100000
#define TT     625                   // 25*25
#define GMAX   512

__device__ float4 g_nodes[NMAX];    // {pos.x, pos.y, pos.z, bitcast(atom_type)}
__device__ int    g_bnd[GMAX + 1];  // g_bnd[g] = first edge index of segment g
__device__ int    g_is64;           // 1 if index arrays are int64, 0 if int32

// ---------------------------------------------------------------------------
// Dtype detection: int32 data read as int64 yields values >= N.
// ---------------------------------------------------------------------------
__global__ void detect_kernel(const long long* __restrict__ mapping, int N)
{
    bool ok64 = true;
    #pragma unroll
    for (int i = 0; i < 8; i++) {
        long long v = mapping[i];
        if (v < 0 || v >= (long long)N) ok64 = false;
    }
    g_is64 = ok64 ? 1 : 0;
}
__device__ __forceinline__ int read_flag() { return *(volatile int*)&g_is64; }

// ---------------------------------------------------------------------------
// Prep (single kernel, dtype branch inside): zero output, pack node table,
// binary-search segment boundaries.
// ---------------------------------------------------------------------------
template <typename IdxT>
__device__ __forceinline__ void prep_body(const float* __restrict__ pos,
                                          const IdxT* __restrict__ atom_types,
                                          const IdxT* __restrict__ batch,
                                          float* __restrict__ out,
                                          int N, int E, int G)
{
    int i = blockIdx.x * blockDim.x + threadIdx.x;
    if (i < N) {
        float4 v;
        v.x = pos[3 * i + 0];
        v.y = pos[3 * i + 1];
        v.z = pos[3 * i + 2];
        v.w = __int_as_float((int)atom_types[i]);
        g_nodes[i] = v;
    }
    if (i < G) out[i] = 0.0f;
    if (i <= G) {
        int lo = 0, hi = E;
        IdxT target = (IdxT)i;
        while (lo < hi) {
            int mid = (int)(((unsigned)lo + (unsigned)hi) >> 1);
            if (batch[mid] < target) lo = mid + 1; else hi = mid;
        }
        g_bnd[i] = lo;
    }
}

__global__ void prep_kernel(const float* __restrict__ pos,
                            const void* __restrict__ atom_types,
                            const void* __restrict__ batch,
                            float* __restrict__ out,
                            int N, int E, int G)
{
    if (read_flag() == 0)
        prep_body<int>(pos, (const int*)atom_types, (const int*)batch, out, N, E, G);
    else
        prep_body<long long>(pos, (const long long*)atom_types, (const long long*)batch, out, N, E, G);
}

// ---------------------------------------------------------------------------
// Shared fragments
// ---------------------------------------------------------------------------
#define EDGE_V(II, JJ, VOUT)                                               \
    do {                                                                   \
        float4 p = __ldg(nodes + (II));                                    \
        float4 q = __ldg(nodes + (JJ));                                    \
        float dx = p.x - q.x, dy = p.y - q.y, dz = p.z - q.z;              \
        float r2 = fmaf(dx, dx, fmaf(dy, dy, dz * dz));                    \
        float x  = sqrtf(r2);                                              \
        int idx  = __float_as_int(p.w) * 25 + __float_as_int(q.w);         \
        float4 k = sk[idx];                                                \
        float  c = sv[idx];                                                \
        (VOUT) = fmaf(x, fmaf(x, fmaf(x, fmaf(x, k.w, k.z), k.y), k.x), c);\
    } while (0)

#define HANDLE1(EIDX, VVAL)                                                \
    do {                                                                   \
        if ((EIDX) >= bndEnd) {                                            \
            if (acc != 0.0f) atomicAdd(&out[seg], acc);                    \
            acc = 0.0f;                                                    \
            do { seg++; } while ((EIDX) >= sbnd[seg + 1]);                 \
            bndEnd = sbnd[seg + 1];                                        \
        }                                                                  \
        acc += (VVAL);                                                     \
    } while (0)

// Warp-aggregated final flush: one atomic per warp when segment is uniform.
__device__ __forceinline__ void flush_acc(float* __restrict__ out, int seg, float acc)
{
    const unsigned full = 0xFFFFFFFFu;
    int seg0 = __shfl_sync(full, seg, 0);
    bool uniform = __all_sync(full, seg == seg0);
    if (uniform) {
        #pragma unroll
        for (int o = 16; o > 0; o >>= 1)
            acc += __shfl_xor_sync(full, acc, o);
        if ((threadIdx.x & 31) == 0 && acc != 0.0f)
            atomicAdd(&out[seg0], acc);
    } else {
        if (acc != 0.0f) atomicAdd(&out[seg], acc);
    }
}

// ---------------------------------------------------------------------------
// 4-index vector loads
// ---------------------------------------------------------------------------
template <typename IdxT> struct Ld4;
template <> struct Ld4<int> {
    static __device__ __forceinline__ void load(const int* p, int4& o) {
        o = __ldcs((const int4*)p);
    }
};
template <> struct Ld4<long long> {
    static __device__ __forceinline__ void load(const long long* p, int4& o) {
        longlong2 a = __ldcs((const longlong2*)p);
        longlong2 b = __ldcs((const longlong2*)(p + 2));
        o.x = (int)a.x; o.y = (int)a.y; o.z = (int)b.x; o.w = (int)b.y;
    }
};

// ---------------------------------------------------------------------------
// Edge body (shared by both dtypes)
// ---------------------------------------------------------------------------
template <typename IdxT>
__device__ __forceinline__ void edge_body(const IdxT* __restrict__ map0,
                                          const IdxT* __restrict__ map1,
                                          float* __restrict__ out,
                                          int E, int G,
                                          const float4* sk, const float* sv,
                                          const int* sbnd)
{
    const int tid  = threadIdx.x;
    const int tile = blockIdx.x * TILE;
    if (tile >= E) return;

    // initial segment for this thread's first edge
    int firstE = tile + tid * VEC;
    if (firstE >= E) firstE = E - 1;
    int lo = 0, hi = G - 1;
    while (lo < hi) {
        int mid = (lo + hi) >> 1;
        if (sbnd[mid + 1] <= firstE) lo = mid + 1; else hi = mid;
    }
    int   seg    = lo;
    int   bndEnd = sbnd[seg + 1];
    float acc    = 0.0f;

    const float4* __restrict__ nodes = g_nodes;

    if (tile + TILE <= E) {
        #pragma unroll
        for (int it = 0; it < ITERS; ++it) {
            const int e = tile + it * (TPB * VEC) + tid * VEC;
            int4 ia, ja;
            Ld4<IdxT>::load(map0 + e, ia);
            Ld4<IdxT>::load(map1 + e, ja);

            float V0, V1, V2, V3;
            EDGE_V(ia.x, ja.x, V0);
            EDGE_V(ia.y, ja.y, V1);
            EDGE_V(ia.z, ja.z, V2);
            EDGE_V(ia.w, ja.w, V3);

            if (e + 3 < bndEnd) {
                acc += (V0 + V1) + (V2 + V3);
            } else {
                HANDLE1(e + 0, V0);
                HANDLE1(e + 1, V1);
                HANDLE1(e + 2, V2);
                HANDLE1(e + 3, V3);
            }
        }
    } else {
        for (int it = 0; it < ITERS; ++it) {
            int e = tile + it * (TPB * VEC) + tid * VEC;
            for (int kk = 0; kk < VEC; ++kk) {
                int ee = e + kk;
                if (ee >= E) break;
                int ii = (int)__ldcs(map0 + ee);
                int jj = (int)__ldcs(map1 + ee);
                float V;
                EDGE_V(ii, jj, V);
                HANDLE1(ee, V);
            }
        }
    }

    flush_acc(out, seg, acc);
}

// ---------------------------------------------------------------------------
// Single edge kernel, dtype branch inside (uniform per grid)
// ---------------------------------------------------------------------------
__global__ void __launch_bounds__(TPB, 8)
edge_kernel(const void* __restrict__ mapping,
            const float* __restrict__ ks,     // [4,25,25]
            const float* __restrict__ v0t,    // [25,25]
            float* __restrict__ out,
            int E, int G)
{
    __shared__ float4 sk[TT];
    __shared__ float  sv[TT];
    __shared__ int    sbnd[GMAX + 1];

    const int tid = threadIdx.x;
    for (int i = tid; i < TT; i += TPB) {
        sk[i] = make_float4(ks[i], ks[TT + i], ks[2 * TT + i], ks[3 * TT + i]);
        sv[i] = v0t[i];
    }
    for (int i = tid; i <= G; i += TPB) sbnd[i] = g_bnd[i];
    __syncthreads();

    if (read_flag() == 0) {
        const int* m = (const int*)mapping;
        edge_body<int>(m, m + E, out, E, G, sk, sv, sbnd);
    } else {
        const long long* m = (const long long*)mapping;
        edge_body<long long>(m, m + E, out, E, G, sk, sv, sbnd);
    }
}

// ---------------------------------------------------------------------------
// Launch
// ---------------------------------------------------------------------------
extern "C" void kernel_launch(void* const* d_in, const int* in_sizes, int n_in,
                              void* d_out, int out_size)
{
    const float* pos = (const float*)d_in[0];
    const float* ks  = (const float*)d_in[1];
    const float* v0t = (const float*)d_in[2];
    const void*  mapping    = d_in[3];
    const void*  atom_types = d_in[4];
    const void*  batch      = d_in[5];

    const int N = in_sizes[0] / 3;
    const int E = in_sizes[3] / 2;
    const int G = out_size;

    float* out = (float*)d_out;

    detect_kernel<<<1, 1>>>((const long long*)mapping, N);

    int prepThreads = (N > G + 1) ? N : (G + 1);
    int prepBlocks  = (prepThreads + TPB - 1) / TPB;
    prep_kernel<<<prepBlocks, TPB>>>(pos, atom_types, batch, out, N, E, G);

    int blocks = (E + TILE - 1) / TILE;
    edge_kernel<<<blocks, TPB>>>(mapping, ks, v0t, out, E, G);
}

// round 10
// speedup vs baseline: 1.0508x; 1.0508x over previous
#include <cuda_runtime.h>
#include <cuda_bf16.h>
#include <stdint.h>

// Dataset-fixed: N=100000, T=25, DEGS=4, G=512, E=8000000
#define TPB    256
#define VEC    4                     // edges per thread per inner iteration
#define ITERS  4                     // inner iterations per tile
#define TILE   (TPB * VEC * ITERS)   // 4096 edges per block
#define NMAX   100000
#define TT     625                   // 25*25
#define GMAX   512

__device__ float4 g_nodes[NMAX];    // {pos.x, pos.y, pos.z, bitcast(atom_type)}
__device__ int    g_bnd[GMAX + 1];  // g_bnd[g] = first edge index of segment g
__device__ int    g_is64;           // 1 if index arrays are int64, 0 if int32

// ---------------------------------------------------------------------------
// Local dtype detection: int32 data read as int64 yields values >= N.
// Cheap enough to run per-thread (loads broadcast & L1-hot).
// ---------------------------------------------------------------------------
__device__ __forceinline__ int detect_is64(const long long* __restrict__ mapping, int N)
{
    bool ok64 = true;
    #pragma unroll
    for (int i = 0; i < 8; i++) {
        long long v = __ldg(mapping + i);
        if (v < 0 || v >= (long long)N) ok64 = false;
    }
    return ok64 ? 1 : 0;
}

__device__ __forceinline__ int read_flag() { return *(volatile int*)&g_is64; }

// ---------------------------------------------------------------------------
// Prep (detect folded in): zero output, pack node table, segment boundaries,
// publish dtype flag for the edge kernels.
// ---------------------------------------------------------------------------
template <typename IdxT>
__device__ __forceinline__ void prep_body(const float* __restrict__ pos,
                                          const IdxT* __restrict__ atom_types,
                                          const IdxT* __restrict__ batch,
                                          float* __restrict__ out,
                                          int N, int E, int G)
{
    int i = blockIdx.x * blockDim.x + threadIdx.x;
    if (i < N) {
        float4 v;
        v.x = pos[3 * i + 0];
        v.y = pos[3 * i + 1];
        v.z = pos[3 * i + 2];
        v.w = __int_as_float((int)atom_types[i]);
        g_nodes[i] = v;
    }
    if (i < G) out[i] = 0.0f;
    if (i <= G) {
        int lo = 0, hi = E;
        IdxT target = (IdxT)i;
        while (lo < hi) {
            int mid = (int)(((unsigned)lo + (unsigned)hi) >> 1);
            if (batch[mid] < target) lo = mid + 1; else hi = mid;
        }
        g_bnd[i] = lo;
    }
}

__global__ void prep_kernel(const float* __restrict__ pos,
                            const void* __restrict__ atom_types,
                            const void* __restrict__ batch,
                            const void* __restrict__ mapping,
                            float* __restrict__ out,
                            int N, int E, int G)
{
    int is64 = detect_is64((const long long*)mapping, N);
    if (blockIdx.x == 0 && threadIdx.x == 0) g_is64 = is64;

    if (is64 == 0)
        prep_body<int>(pos, (const int*)atom_types, (const int*)batch, out, N, E, G);
    else
        prep_body<long long>(pos, (const long long*)atom_types, (const long long*)batch, out, N, E, G);
}

// ---------------------------------------------------------------------------
// Shared fragments
// ---------------------------------------------------------------------------
#define EDGE_V(II, JJ, VOUT)                                               \
    do {                                                                   \
        float4 p = __ldg(nodes + (II));                                    \
        float4 q = __ldg(nodes + (JJ));                                    \
        float dx = p.x - q.x, dy = p.y - q.y, dz = p.z - q.z;              \
        float r2 = fmaf(dx, dx, fmaf(dy, dy, dz * dz));                    \
        float x  = sqrtf(r2);                                              \
        int idx  = __float_as_int(p.w) * 25 + __float_as_int(q.w);         \
        float4 k = sk[idx];                                                \
        float  c = sv[idx];                                                \
        (VOUT) = fmaf(x, fmaf(x, fmaf(x, fmaf(x, k.w, k.z), k.y), k.x), c);\
    } while (0)

#define HANDLE1(EIDX, VVAL)                                                \
    do {                                                                   \
        if ((EIDX) >= bndEnd) {                                            \
            if (acc != 0.0f) atomicAdd(&out[seg], acc);                    \
            acc = 0.0f;                                                    \
            do { seg++; } while ((EIDX) >= sbnd[seg + 1]);                 \
            bndEnd = sbnd[seg + 1];                                        \
        }                                                                  \
        acc += (VVAL);                                                     \
    } while (0)

// Warp-aggregated final flush: one atomic per warp when segment is uniform.
__device__ __forceinline__ void flush_acc(float* __restrict__ out, int seg, float acc)
{
    const unsigned full = 0xFFFFFFFFu;
    int seg0 = __shfl_sync(full, seg, 0);
    bool uniform = __all_sync(full, seg == seg0);
    if (uniform) {
        #pragma unroll
        for (int o = 16; o > 0; o >>= 1)
            acc += __shfl_xor_sync(full, acc, o);
        if ((threadIdx.x & 31) == 0 && acc != 0.0f)
            atomicAdd(&out[seg0], acc);
    } else {
        if (acc != 0.0f) atomicAdd(&out[seg], acc);
    }
}

// ---------------------------------------------------------------------------
// Main int32 edge kernel — identical to R8 (87.0us measured)
// ---------------------------------------------------------------------------
__global__ void __launch_bounds__(TPB, 8)
edge_kernel32(const int* __restrict__ map0,
              const int* __restrict__ map1,
              const float* __restrict__ ks,     // [4,25,25]
              const float* __restrict__ v0t,    // [25,25]
              float* __restrict__ out,
              int E, int G)
{
    if (read_flag() != 0) return;

    __shared__ float4 sk[TT];
    __shared__ float  sv[TT];
    __shared__ int    sbnd[GMAX + 1];

    const int tid = threadIdx.x;
    for (int i = tid; i < TT; i += TPB) {
        sk[i] = make_float4(ks[i], ks[TT + i], ks[2 * TT + i], ks[3 * TT + i]);
        sv[i] = v0t[i];
    }
    for (int i = tid; i <= G; i += TPB) sbnd[i] = g_bnd[i];
    __syncthreads();

    const int tile = blockIdx.x * TILE;
    if (tile >= E) return;

    int firstE = tile + tid * VEC;
    if (firstE >= E) firstE = E - 1;
    int lo = 0, hi = G - 1;
    while (lo < hi) {
        int mid = (lo + hi) >> 1;
        if (sbnd[mid + 1] <= firstE) lo = mid + 1; else hi = mid;
    }
    int   seg    = lo;
    int   bndEnd = sbnd[seg + 1];
    float acc    = 0.0f;

    const float4* __restrict__ nodes = g_nodes;

    if (tile + TILE <= E) {
        #pragma unroll
        for (int it = 0; it < ITERS; ++it) {
            const int e = tile + it * (TPB * VEC) + tid * VEC;
            int4 ia = __ldcs((const int4*)(map0 + e));
            int4 ja = __ldcs((const int4*)(map1 + e));

            float V0, V1, V2, V3;
            EDGE_V(ia.x, ja.x, V0);
            EDGE_V(ia.y, ja.y, V1);
            EDGE_V(ia.z, ja.z, V2);
            EDGE_V(ia.w, ja.w, V3);

            if (e + 3 < bndEnd) {
                acc += (V0 + V1) + (V2 + V3);
            } else {
                HANDLE1(e + 0, V0);
                HANDLE1(e + 1, V1);
                HANDLE1(e + 2, V2);
                HANDLE1(e + 3, V3);
            }
        }
    } else {
        for (int it = 0; it < ITERS; ++it) {
            int e = tile + it * (TPB * VEC) + tid * VEC;
            for (int kk = 0; kk < VEC; ++kk) {
                int ee = e + kk;
                if (ee >= E) break;
                int ii = __ldcs(map0 + ee);
                int jj = __ldcs(map1 + ee);
                float V;
                EDGE_V(ii, jj, V);
                HANDLE1(ee, V);
            }
        }
    }

    flush_acc(out, seg, acc);
}

// ---------------------------------------------------------------------------
// int64 fallback (early-exits when data is int32)
// ---------------------------------------------------------------------------
__global__ void __launch_bounds__(TPB)
edge_kernel64(const long long* __restrict__ map0,
              const long long* __restrict__ map1,
              const float* __restrict__ ks,
              const float* __restrict__ v0t,
              float* __restrict__ out,
              int E, int G)
{
    if (read_flag() != 1) return;

    __shared__ float4 sk[TT];
    __shared__ float  sv[TT];
    __shared__ int    sbnd[GMAX + 1];

    const int tid = threadIdx.x;
    for (int i = tid; i < TT; i += TPB) {
        sk[i] = make_float4(ks[i], ks[TT + i], ks[2 * TT + i], ks[3 * TT + i]);
        sv[i] = v0t[i];
    }
    for (int i = tid; i <= G; i += TPB) sbnd[i] = g_bnd[i];
    __syncthreads();

    const int tile = blockIdx.x * TILE;
    if (tile >= E) return;

    int firstE = tile + tid * VEC;
    if (firstE >= E) firstE = E - 1;
    int lo = 0, hi = G - 1;
    while (lo < hi) {
        int mid = (lo + hi) >> 1;
        if (sbnd[mid + 1] <= firstE) lo = mid + 1; else hi = mid;
    }
    int   seg    = lo;
    int   bndEnd = sbnd[seg + 1];
    float acc    = 0.0f;

    const float4* __restrict__ nodes = g_nodes;

    for (int it = 0; it < ITERS; ++it) {
        int e = tile + it * (TPB * VEC) + tid * VEC;
        if (e >= E) break;
        if (e + VEC <= E) {
            longlong2 a0 = __ldcs((const longlong2*)(map0 + e));
            longlong2 a1 = __ldcs((const longlong2*)(map0 + e + 2));
            longlong2 b0 = __ldcs((const longlong2*)(map1 + e));
            longlong2 b1 = __ldcs((const longlong2*)(map1 + e + 2));
            float V0, V1, V2, V3;
            EDGE_V((int)a0.x, (int)b0.x, V0);
            EDGE_V((int)a0.y, (int)b0.y, V1);
            EDGE_V((int)a1.x, (int)b1.x, V2);
            EDGE_V((int)a1.y, (int)b1.y, V3);
            if (e + 3 < bndEnd) {
                acc += (V0 + V1) + (V2 + V3);
            } else {
                HANDLE1(e + 0, V0);
                HANDLE1(e + 1, V1);
                HANDLE1(e + 2, V2);
                HANDLE1(e + 3, V3);
            }
        } else {
            for (int kk = 0; kk < VEC; ++kk) {
                int ee = e + kk;
                if (ee >= E) break;
                int ii = (int)__ldcs(map0 + ee);
                int jj = (int)__ldcs(map1 + ee);
                float V;
                EDGE_V(ii, jj, V);
                HANDLE1(ee, V);
            }
        }
    }
    if (acc != 0.0f) atomicAdd(&out[seg], acc);
}

// ---------------------------------------------------------------------------
// Launch: 2 kernels total (prep w/ inline detect, then edge pair)
// ---------------------------------------------------------------------------
extern "C" void kernel_launch(void* const* d_in, const int* in_sizes, int n_in,
                              void* d_out, int out_size)
{
    const float* pos = (const float*)d_in[0];
    const float* ks  = (const float*)d_in[1];
    const float* v0t = (const float*)d_in[2];
    const void*  mapping    = d_in[3];
    const void*  atom_types = d_in[4];
    const void*  batch      = d_in[5];

    const int N = in_sizes[0] / 3;
    const int E = in_sizes[3] / 2;
    const int G = out_size;

    float* out = (float*)d_out;

    int prepThreads = (N > G + 1) ? N : (G + 1);
    int prepBlocks  = (prepThreads + TPB - 1) / TPB;
    prep_kernel<<<prepBlocks, TPB>>>(pos, atom_types, batch, mapping, out, N, E, G);

    int blocks = (E + TILE - 1) / TILE;
    edge_kernel32<<<blocks, TPB>>>(
        (const int*)mapping, (const int*)mapping + E, ks, v0t, out, E, G);
    edge_kernel64<<<blocks, TPB>>>(
        (const long long*)mapping, (const long long*)mapping + E, ks, v0t, out, E, G);
}

// round 11
// speedup vs baseline: 1.0703x; 1.0185x over previous
#include <cuda_runtime.h>
#include <cuda_bf16.h>
#include <stdint.h>

// Dataset-fixed: N=100000, T=25, DEGS=4, G=512, E=8000000
#define TPB    256
#define VEC    4                     // edges per thread per inner iteration
#define ITERS  4                     // inner iterations per tile
#define TILE   (TPB * VEC * ITERS)   // 4096 edges per block
#define NMAX   100000
#define TT     625                   // 25*25
#define GMAX   512

__device__ float4 g_nodes[NMAX];    // {pos.x, pos.y, pos.z, bitcast(atom_type)}
__device__ int    g_bnd[GMAX + 1];  // g_bnd[g] = first edge index of segment g
__device__ int    g_is64;           // 1 if index arrays are int64, 0 if int32

// ---------------------------------------------------------------------------
// Local dtype detection: int32 data read as int64 yields values >= N.
// ---------------------------------------------------------------------------
__device__ __forceinline__ int detect_is64(const long long* __restrict__ mapping, int N)
{
    bool ok64 = true;
    #pragma unroll
    for (int i = 0; i < 8; i++) {
        long long v = __ldg(mapping + i);
        if (v < 0 || v >= (long long)N) ok64 = false;
    }
    return ok64 ? 1 : 0;
}

__device__ __forceinline__ int read_flag() { return *(volatile int*)&g_is64; }

// ---------------------------------------------------------------------------
// Warp-cooperative lower_bound: 32-ary search, ~5 dependent rounds for E=8M.
// Invariant: batch[lo-1] < target (virtually batch[-1] = -inf),
//            lower_bound in [lo, lo+len].
// ---------------------------------------------------------------------------
template <typename IdxT>
__device__ __forceinline__ int warp_lower_bound(const IdxT* __restrict__ batch,
                                                int E, IdxT target, int lane)
{
    const unsigned full = 0xFFFFFFFFu;
    int lo = 0, len = E;
    while (len > 0) {
        int step  = (len + 31) >> 5;            // ceil(len/32)
        int probe = lo + lane * step;
        bool lt = false;
        if (lane * step < len)                  // probe < lo+len <= E
            lt = (__ldg(batch + probe) < target);
        unsigned ballot = __ballot_sync(full, lt);
        if (ballot == 0) return lo;             // batch[lo] >= target -> done
        int kmax = 31 - __clz(ballot);          // highest lane with value < target
        int up   = (kmax + 1) * step; if (up > len) up = len;   // relative upper
        int nlo  = kmax * step + 1;             // relative new lower
        lo  += nlo;
        len  = up - nlo;
    }
    return lo;
}

// ---------------------------------------------------------------------------
// Prep: detect dtype, zero output, pack node table, warp-parallel boundaries.
// ---------------------------------------------------------------------------
template <typename IdxT>
__device__ __forceinline__ void prep_body(const float* __restrict__ pos,
                                          const IdxT* __restrict__ atom_types,
                                          const IdxT* __restrict__ batch,
                                          float* __restrict__ out,
                                          int N, int E, int G)
{
    int i = blockIdx.x * blockDim.x + threadIdx.x;
    if (i < N) {
        float4 v;
        v.x = pos[3 * i + 0];
        v.y = pos[3 * i + 1];
        v.z = pos[3 * i + 2];
        v.w = __int_as_float((int)atom_types[i]);
        g_nodes[i] = v;
    }
    if (i < G) out[i] = 0.0f;

    // one warp per boundary target g in [0, G]
    int warpId = i >> 5;
    int lane   = i & 31;
    if (warpId <= G) {
        int b = warp_lower_bound<IdxT>(batch, E, (IdxT)warpId, lane);
        if (lane == 0) g_bnd[warpId] = b;
    }
}

__global__ void prep_kernel(const float* __restrict__ pos,
                            const void* __restrict__ atom_types,
                            const void* __restrict__ batch,
                            const void* __restrict__ mapping,
                            float* __restrict__ out,
                            int N, int E, int G)
{
    int is64 = detect_is64((const long long*)mapping, N);
    if (blockIdx.x == 0 && threadIdx.x == 0) g_is64 = is64;

    if (is64 == 0)
        prep_body<int>(pos, (const int*)atom_types, (const int*)batch, out, N, E, G);
    else
        prep_body<long long>(pos, (const long long*)atom_types, (const long long*)batch, out, N, E, G);
}

// ---------------------------------------------------------------------------
// Shared fragments
// ---------------------------------------------------------------------------
#define EDGE_V(II, JJ, VOUT)                                               \
    do {                                                                   \
        float4 p = __ldg(nodes + (II));                                    \
        float4 q = __ldg(nodes + (JJ));                                    \
        float dx = p.x - q.x, dy = p.y - q.y, dz = p.z - q.z;              \
        float r2 = fmaf(dx, dx, fmaf(dy, dy, dz * dz));                    \
        float x  = sqrtf(r2);                                              \
        int idx  = __float_as_int(p.w) * 25 + __float_as_int(q.w);         \
        float4 k = sk[idx];                                                \
        float  c = sv[idx];                                                \
        (VOUT) = fmaf(x, fmaf(x, fmaf(x, fmaf(x, k.w, k.z), k.y), k.x), c);\
    } while (0)

#define HANDLE1(EIDX, VVAL)                                                \
    do {                                                                   \
        if ((EIDX) >= bndEnd) {                                            \
            if (acc != 0.0f) atomicAdd(&out[seg], acc);                    \
            acc = 0.0f;                                                    \
            do { seg++; } while ((EIDX) >= sbnd[seg + 1]);                 \
            bndEnd = sbnd[seg + 1];                                        \
        }                                                                  \
        acc += (VVAL);                                                     \
    } while (0)

// Warp-aggregated final flush: one atomic per warp when segment is uniform.
__device__ __forceinline__ void flush_acc(float* __restrict__ out, int seg, float acc)
{
    const unsigned full = 0xFFFFFFFFu;
    int seg0 = __shfl_sync(full, seg, 0);
    bool uniform = __all_sync(full, seg == seg0);
    if (uniform) {
        #pragma unroll
        for (int o = 16; o > 0; o >>= 1)
            acc += __shfl_xor_sync(full, acc, o);
        if ((threadIdx.x & 31) == 0 && acc != 0.0f)
            atomicAdd(&out[seg0], acc);
    } else {
        if (acc != 0.0f) atomicAdd(&out[seg], acc);
    }
}

// ---------------------------------------------------------------------------
// Main int32 edge kernel — identical to R8 (87.0us measured)
// ---------------------------------------------------------------------------
__global__ void __launch_bounds__(TPB, 8)
edge_kernel32(const int* __restrict__ map0,
              const int* __restrict__ map1,
              const float* __restrict__ ks,     // [4,25,25]
              const float* __restrict__ v0t,    // [25,25]
              float* __restrict__ out,
              int E, int G)
{
    if (read_flag() != 0) return;

    __shared__ float4 sk[TT];
    __shared__ float  sv[TT];
    __shared__ int    sbnd[GMAX + 1];

    const int tid = threadIdx.x;
    for (int i = tid; i < TT; i += TPB) {
        sk[i] = make_float4(ks[i], ks[TT + i], ks[2 * TT + i], ks[3 * TT + i]);
        sv[i] = v0t[i];
    }
    for (int i = tid; i <= G; i += TPB) sbnd[i] = g_bnd[i];
    __syncthreads();

    const int tile = blockIdx.x * TILE;
    if (tile >= E) return;

    int firstE = tile + tid * VEC;
    if (firstE >= E) firstE = E - 1;
    int lo = 0, hi = G - 1;
    while (lo < hi) {
        int mid = (lo + hi) >> 1;
        if (sbnd[mid + 1] <= firstE) lo = mid + 1; else hi = mid;
    }
    int   seg    = lo;
    int   bndEnd = sbnd[seg + 1];
    float acc    = 0.0f;

    const float4* __restrict__ nodes = g_nodes;

    if (tile + TILE <= E) {
        #pragma unroll
        for (int it = 0; it < ITERS; ++it) {
            const int e = tile + it * (TPB * VEC) + tid * VEC;
            int4 ia = __ldcs((const int4*)(map0 + e));
            int4 ja = __ldcs((const int4*)(map1 + e));

            float V0, V1, V2, V3;
            EDGE_V(ia.x, ja.x, V0);
            EDGE_V(ia.y, ja.y, V1);
            EDGE_V(ia.z, ja.z, V2);
            EDGE_V(ia.w, ja.w, V3);

            if (e + 3 < bndEnd) {
                acc += (V0 + V1) + (V2 + V3);
            } else {
                HANDLE1(e + 0, V0);
                HANDLE1(e + 1, V1);
                HANDLE1(e + 2, V2);
                HANDLE1(e + 3, V3);
            }
        }
    } else {
        for (int it = 0; it < ITERS; ++it) {
            int e = tile + it * (TPB * VEC) + tid * VEC;
            for (int kk = 0; kk < VEC; ++kk) {
                int ee = e + kk;
                if (ee >= E) break;
                int ii = __ldcs(map0 + ee);
                int jj = __ldcs(map1 + ee);
                float V;
                EDGE_V(ii, jj, V);
                HANDLE1(ee, V);
            }
        }
    }

    flush_acc(out, seg, acc);
}

// ---------------------------------------------------------------------------
// int64 fallback (early-exits when data is int32)
// ---------------------------------------------------------------------------
__global__ void __launch_bounds__(TPB)
edge_kernel64(const long long* __restrict__ map0,
              const long long* __restrict__ map1,
              const float* __restrict__ ks,
              const float* __restrict__ v0t,
              float* __restrict__ out,
              int E, int G)
{
    if (read_flag() != 1) return;

    __shared__ float4 sk[TT];
    __shared__ float  sv[TT];
    __shared__ int    sbnd[GMAX + 1];

    const int tid = threadIdx.x;
    for (int i = tid; i < TT; i += TPB) {
        sk[i] = make_float4(ks[i], ks[TT + i], ks[2 * TT + i], ks[3 * TT + i]);
        sv[i] = v0t[i];
    }
    for (int i = tid; i <= G; i += TPB) sbnd[i] = g_bnd[i];
    __syncthreads();

    const int tile = blockIdx.x * TILE;
    if (tile >= E) return;

    int firstE = tile + tid * VEC;
    if (firstE >= E) firstE = E - 1;
    int lo = 0, hi = G - 1;
    while (lo < hi) {
        int mid = (lo + hi) >> 1;
        if (sbnd[mid + 1] <= firstE) lo = mid + 1; else hi = mid;
    }
    int   seg    = lo;
    int   bndEnd = sbnd[seg + 1];
    float acc    = 0.0f;

    const float4* __restrict__ nodes = g_nodes;

    for (int it = 0; it < ITERS; ++it) {
        int e = tile + it * (TPB * VEC) + tid * VEC;
        if (e >= E) break;
        if (e + VEC <= E) {
            longlong2 a0 = __ldcs((const longlong2*)(map0 + e));
            longlong2 a1 = __ldcs((const longlong2*)(map0 + e + 2));
            longlong2 b0 = __ldcs((const longlong2*)(map1 + e));
            longlong2 b1 = __ldcs((const longlong2*)(map1 + e + 2));
            float V0, V1, V2, V3;
            EDGE_V((int)a0.x, (int)b0.x, V0);
            EDGE_V((int)a0.y, (int)b0.y, V1);
            EDGE_V((int)a1.x, (int)b1.x, V2);
            EDGE_V((int)a1.y, (int)b1.y, V3);
            if (e + 3 < bndEnd) {
                acc += (V0 + V1) + (V2 + V3);
            } else {
                HANDLE1(e + 0, V0);
                HANDLE1(e + 1, V1);
                HANDLE1(e + 2, V2);
                HANDLE1(e + 3, V3);
            }
        } else {
            for (int kk = 0; kk < VEC; ++kk) {
                int ee = e + kk;
                if (ee >= E) break;
                int ii = (int)__ldcs(map0 + ee);
                int jj = (int)__ldcs(map1 + ee);
                float V;
                EDGE_V(ii, jj, V);
                HANDLE1(ee, V);
            }
        }
    }
    if (acc != 0.0f) atomicAdd(&out[seg], acc);
}

// ---------------------------------------------------------------------------
// Launch
// ---------------------------------------------------------------------------
extern "C" void kernel_launch(void* const* d_in, const int* in_sizes, int n_in,
                              void* d_out, int out_size)
{
    const float* pos = (const float*)d_in[0];
    const float* ks  = (const float*)d_in[1];
    const float* v0t = (const float*)d_in[2];
    const void*  mapping    = d_in[3];
    const void*  atom_types = d_in[4];
    const void*  batch      = d_in[5];

    const int N = in_sizes[0] / 3;
    const int E = in_sizes[3] / 2;
    const int G = out_size;

    float* out = (float*)d_out;

    int prepThreads = (N > (G + 1) * 32) ? N : (G + 1) * 32;
    int prepBlocks  = (prepThreads + TPB - 1) / TPB;
    prep_kernel<<<prepBlocks, TPB>>>(pos, atom_types, batch, mapping, out, N, E, G);

    int blocks = (E + TILE - 1) / TILE;
    edge_kernel32<<<blocks, TPB>>>(
        (const int*)mapping, (const int*)mapping + E, ks, v0t, out, E, G);
    edge_kernel64<<<blocks, TPB>>>(
        (const long long*)mapping, (const long long*)mapping + E, ks, v0t, out, E, G);
}